// round 14
// baseline (speedup 1.0000x reference)
#include <cuda_runtime.h>
#include <cuda_bf16.h>

#define OUT_CH 128
#define TPB    256
#define TOKB   2048     // tokens per block, 8 per thread
#define CAP    16       // owned edges per pass (multi-pass covers pathology)
#define NSUB   8        // sub-slots per edge (spread same-address atomics)

// Block b owns tokens [2048b, 2048b+2048) and edges (segs[lo-1], segs[hi-1]]
// (block 0 from 0; last block through E-1): exact edge partition for ANY
// sorted segs, empty edges included. Tail edge eB may spill into following
// windows; warp 0 finishes it with a shfl-controlled scan.
// No binary search. Deposits: ONE sub-slotted smem atomic per thread.
// __launch_bounds__(TPB, 6): cap regs ~42 so 6 blocks/SM co-reside (R13 at
// 64 regs ran at occ 40% and was memory-latency-bound).
__global__ void __launch_bounds__(TPB, 6)
fused_edge_mean(const int* __restrict__ tokens,
                const int* __restrict__ segs,
                const float* __restrict__ emb,   // [4][128]
                float* __restrict__ out,         // [E][128]
                int T, int E) {
    __shared__ unsigned long long s_hist[CAP][NSUB];   // 2 KB
    __shared__ unsigned long long s_lut[256];          // 2 KB
    __shared__ int s_eA, s_eB;

    const int tid  = threadIdx.x;
    const int lane = tid & 31;
    const int wid  = tid >> 5;
    const int lo   = blockIdx.x * TOKB;
    if (lo >= T) return;
    const int hi = min(T, lo + TOKB);

    // ---- O(1) ownership probes (two warps, overlap the stream loads) ----
    if (tid == 0)  s_eA = (lo == 0) ? 0 : (__ldg(&segs[lo - 1]) + 1);
    if (tid == 32) s_eB = (hi >= T) ? (E - 1) : __ldg(&segs[hi - 1]);

    // ---- stream loads: 8 contiguous tokens/thread + strip end-probes ----
    const int4* tok4 = (const int4*)tokens;
    const int4* seg4 = (const int4*)segs;
    const int base = lo + tid * 8;
    const int j    = base >> 2;
    const bool full = (base + 8 <= T);
    unsigned pk = 0;                    // 8 tokens x 2 bits, packed at load
    int sfirst = 0, slast = -1;
    if (full) {
        const int4 ta = tok4[j];
        const int4 tb = tok4[j + 1];
        sfirst = __ldg(&segs[base]);        // same 32B sectors as the strip
        slast  = __ldg(&segs[base + 7]);
        pk = (ta.x & 3)         | ((ta.y & 3) << 2)
           | ((ta.z & 3) << 4)  | ((ta.w & 3) << 6)
           | ((tb.x & 3) << 8)  | ((tb.y & 3) << 10)
           | ((tb.z & 3) << 12) | ((tb.w & 3) << 14);
    }

    // LUT + hist zero while loads are in flight.
    // s_lut[i] = sum over i's four 2-bit fields t of (1 << t*16)
    {
        const int t0 = tid & 3, t1 = (tid >> 2) & 3,
                  t2 = (tid >> 4) & 3, t3 = (tid >> 6) & 3;
        s_lut[tid] = (1ull << (t0 * 16)) + (1ull << (t1 * 16))
                   + (1ull << (t2 * 16)) + (1ull << (t3 * 16));
    }
    if (tid < CAP * NSUB) ((unsigned long long*)s_hist)[tid] = 0ull;
    __syncthreads();

    const int eA = s_eA, eB = s_eB;
    const int nown = eB - eA + 1;           // may be <=0: block writes nothing

    for (int cbase = 0; cbase < nown; cbase += CAP) {   // one pass normally
        const int fA = eA + cbase;
        const int fB = min(eB, fA + CAP - 1);
        const unsigned span = (unsigned)(fB - fA);

        // ---- deposit this thread's strip ----
        if (full) {
            if (sfirst == slast) {          // uniform strip (~97%)
                const int le = sfirst - fA;
                if ((unsigned)le <= span)
                    atomicAdd(&s_hist[le][lane & (NSUB - 1)],
                              s_lut[pk & 0xFF] + s_lut[(pk >> 8) & 0xFF]);
            } else {                        // boundary strip: walk runs
                const int4 sa = seg4[j], sb = seg4[j + 1];   // L1 hits
                int cur = sa.x;
                unsigned long long run = 0ull;
#define DEP(C, R)                                                           \
                do {                                                        \
                    const int _le = (C) - fA;                               \
                    if ((R) && (unsigned)_le <= span)                       \
                        atomicAdd(&s_hist[_le][lane & (NSUB - 1)], (R));    \
                } while (0)
#define DOK(SK, K)                                                          \
                do {                                                        \
                    if ((SK) != cur) { DEP(cur, run); run = 0ull; cur = (SK); } \
                    run += 1ull << (((pk >> (2 * (K))) & 3) * 16);          \
                } while (0)
                DOK(sa.x, 0); DOK(sa.y, 1); DOK(sa.z, 2); DOK(sa.w, 3);
                DOK(sb.x, 4); DOK(sb.y, 5); DOK(sb.z, 6); DOK(sb.w, 7);
                DEP(cur, run);
#undef DOK
            }
        } else if (base < T) {              // ragged tail insurance
            for (int k = 0; k < 8 && base + k < T; k++) {
                const int s = __ldg(&segs[base + k]);
                const int le = s - fA;
                if ((unsigned)le <= span)
                    atomicAdd(&s_hist[le][lane & (NSUB - 1)],
                              1ull << ((__ldg(&tokens[base + k]) & 3) * 16));
            }
        }
        __syncthreads();

        // ---- epilogue ----
        const int d = lane * 4;
        const bool tailPass = (fB == eB);
        const int lastInt = tailPass ? fB - 1 : fB;   // warp 0 owns eB's row

        if (wid > 0 || !tailPass) {
            const int stride = tailPass ? 7 : 8;
            const int first  = tailPass ? fA + (wid - 1) : fA + wid;
            for (int e = first; e <= lastInt; e += stride) {
                const int le = e - fA;
                unsigned long long h = 0ull;
#pragma unroll
                for (int q = 0; q < NSUB; q++) h += s_hist[le][q];

                const float f0 = (float)((unsigned)(h      ) & 0xFFFFu);
                const float f1 = (float)((unsigned)(h >> 16) & 0xFFFFu);
                const float f2 = (float)((unsigned)(h >> 32) & 0xFFFFu);
                const float f3 = (float)((unsigned)(h >> 48) & 0xFFFFu);
                const float inv = 1.0f / fmaxf(f0 + f1 + f2 + f3, 1.0f);

                const float4 v0 = *(const float4*)(emb + 0 * OUT_CH + d);
                const float4 v1 = *(const float4*)(emb + 1 * OUT_CH + d);
                const float4 v2 = *(const float4*)(emb + 2 * OUT_CH + d);
                const float4 v3 = *(const float4*)(emb + 3 * OUT_CH + d);
                float4 r;
                r.x = (f0 * v0.x + f1 * v1.x + f2 * v2.x + f3 * v3.x) * inv;
                r.y = (f0 * v0.y + f1 * v1.y + f2 * v2.y + f3 * v3.y) * inv;
                r.z = (f0 * v0.z + f1 * v1.z + f2 * v2.z + f3 * v3.z) * inv;
                r.w = (f0 * v0.w + f1 * v1.w + f2 * v2.w + f3 * v3.w) * inv;
                *(float4*)(out + (long long)e * OUT_CH + d) = r;
            }
        }

        if (wid == 0 && tailPass) {
            // finish eB's spill into following windows, then write its row
            unsigned long long ext = 0ull;
            int pos = hi;
            while (pos < T) {
                const int idx = pos + lane * 4;
                int4 s4 = make_int4(-1, -1, -1, -1), t4;
                if (idx < T) {
                    const int jj = (pos >> 2) + lane;
                    s4 = seg4[jj]; t4 = tok4[jj];
                    if (s4.x == eB)                ext += 1ull << ((t4.x & 3) * 16);
                    if (idx + 1 < T && s4.y == eB) ext += 1ull << ((t4.y & 3) * 16);
                    if (idx + 2 < T && s4.z == eB) ext += 1ull << ((t4.z & 3) * 16);
                    if (idx + 3 < T && s4.w == eB) ext += 1ull << ((t4.w & 3) * 16);
                }
                const int lastIdx  = min(T, pos + 128) - 1;
                const int lastLane = (lastIdx - pos) >> 2;
                int sl = -1;
                if (lane == lastLane) {
                    const int rix = lastIdx - idx;
                    sl = (rix == 0) ? s4.x : (rix == 1) ? s4.y
                       : (rix == 2) ? s4.z : s4.w;
                }
                sl = __shfl_sync(0xFFFFFFFFu, sl, lastLane);
                pos += 128;
                if (sl != eB) break;
            }
            const unsigned xlo = __reduce_add_sync(0xFFFFFFFFu, (unsigned)ext);
            const unsigned xhi = __reduce_add_sync(0xFFFFFFFFu, (unsigned)(ext >> 32));

            unsigned long long h = 0ull;
#pragma unroll
            for (int q = 0; q < NSUB; q++) h += s_hist[eB - fA][q];

            const float f0 = (float)(((unsigned)(h      ) & 0xFFFFu) + (xlo & 0xFFFFu));
            const float f1 = (float)(((unsigned)(h >> 16) & 0xFFFFu) + (xlo >> 16));
            const float f2 = (float)(((unsigned)(h >> 32) & 0xFFFFu) + (xhi & 0xFFFFu));
            const float f3 = (float)(((unsigned)(h >> 48) & 0xFFFFu) + (xhi >> 16));
            const float inv = 1.0f / fmaxf(f0 + f1 + f2 + f3, 1.0f);

            const int d0 = lane * 4;
            const float4 v0 = *(const float4*)(emb + 0 * OUT_CH + d0);
            const float4 v1 = *(const float4*)(emb + 1 * OUT_CH + d0);
            const float4 v2 = *(const float4*)(emb + 2 * OUT_CH + d0);
            const float4 v3 = *(const float4*)(emb + 3 * OUT_CH + d0);
            float4 r;
            r.x = (f0 * v0.x + f1 * v1.x + f2 * v2.x + f3 * v3.x) * inv;
            r.y = (f0 * v0.y + f1 * v1.y + f2 * v2.y + f3 * v3.y) * inv;
            r.z = (f0 * v0.z + f1 * v1.z + f2 * v2.z + f3 * v3.z) * inv;
            r.w = (f0 * v0.w + f1 * v1.w + f2 * v2.w + f3 * v3.w) * inv;
            *(float4*)(out + (long long)eB * OUT_CH + d0) = r;
        }

        if (cbase + CAP < nown) {       // pathological multi-pass only
            __syncthreads();
            if (tid < CAP * NSUB) ((unsigned long long*)s_hist)[tid] = 0ull;
            __syncthreads();
        }
    }
}

extern "C" void kernel_launch(void* const* d_in, const int* in_sizes, int n_in,
                              void* d_out, int out_size) {
    // Inputs: 0 overlap_similarity f32[E], 1 overlap_length f32[E],
    //         2 tokens i32[T], 3 segment_ids i32[T], 4 embedding f32[4*128],
    //         5 n_edges
    const int*   tokens = (const int*)d_in[2];
    const int*   segs   = (const int*)d_in[3];
    const float* emb    = (const float*)d_in[4];
    float*       out    = (float*)d_out;

    const int T = in_sizes[2];
    const int E = out_size / OUT_CH;

    const int blocks = (T + TOKB - 1) / TOKB;   // 1024
    fused_edge_mean<<<blocks, TPB>>>(tokens, segs, emb, out, T, E);
}

// round 15
// speedup vs baseline: 1.1905x; 1.1905x over previous
#include <cuda_runtime.h>
#include <cuda_bf16.h>

#define OUT_CH 128
#define TPB    256
#define TOKB   4096     // tokens per block, 16 per thread
#define CAP    32       // owned edges per pass (multi-pass covers pathology)
#define NSUB   8        // sub-slots per edge (spread same-address atomics)

// Block b owns tokens [TOKB*b, TOKB*(b+1)) and edges (segs[lo-1], segs[hi-1]]
// (block 0 from 0; last block through E-1): exact edge partition for ANY
// sorted segs, empty edges included. Tail edge eB may spill into following
// windows; warp 0 finishes it with a shfl-controlled scan.
// No binary search. Deposits: ONE sub-slotted smem atomic per thread (uniform
// path). 16 tokens/thread -> 4 independent LDG.128 + 2 probes per thread
// (deep MLP), grid 512 = single wave at 4 blocks/SM.
__global__ void __launch_bounds__(TPB)
fused_edge_mean(const int* __restrict__ tokens,
                const int* __restrict__ segs,
                const float* __restrict__ emb,   // [4][128]
                float* __restrict__ out,         // [E][128]
                int T, int E) {
    __shared__ unsigned long long s_hist[CAP][NSUB];   // 2 KB
    __shared__ unsigned long long s_lut[256];          // 2 KB
    __shared__ int s_eA, s_eB;

    const int tid  = threadIdx.x;
    const int lane = tid & 31;
    const int wid  = tid >> 5;
    const int lo   = blockIdx.x * TOKB;
    if (lo >= T) return;
    const int hi = min(T, lo + TOKB);

    // ---- O(1) ownership probes (two warps, overlap the stream loads) ----
    if (tid == 0)  s_eA = (lo == 0) ? 0 : (__ldg(&segs[lo - 1]) + 1);
    if (tid == 32) s_eB = (hi >= T) ? (E - 1) : __ldg(&segs[hi - 1]);

    // ---- stream loads: 16 contiguous tokens/thread + strip end-probes ----
    const int4* tok4 = (const int4*)tokens;
    const int4* seg4 = (const int4*)segs;
    const int base = lo + tid * 16;
    const int j    = base >> 2;
    const bool full = (base + 16 <= T);
    unsigned pk = 0;                    // 16 tokens x 2 bits, packed at load
    int sfirst = 0, slast = -1;
    if (full) {
        const int4 ta = tok4[j];
        const int4 tb = tok4[j + 1];
        const int4 tc = tok4[j + 2];
        const int4 td = tok4[j + 3];
        sfirst = __ldg(&segs[base]);        // same sectors as the strip
        slast  = __ldg(&segs[base + 15]);
        pk = (ta.x & 3)         | ((ta.y & 3) << 2)
           | ((ta.z & 3) << 4)  | ((ta.w & 3) << 6)
           | ((tb.x & 3) << 8)  | ((tb.y & 3) << 10)
           | ((tb.z & 3) << 12) | ((tb.w & 3) << 14)
           | ((tc.x & 3) << 16) | ((tc.y & 3) << 18)
           | ((tc.z & 3) << 20) | ((tc.w & 3) << 22)
           | ((td.x & 3) << 24) | ((td.y & 3) << 26)
           | ((td.z & 3) << 28) | ((td.w & 3) << 30);
    }

    // LUT + hist zero while loads are in flight.
    // s_lut[i] = sum over i's four 2-bit fields t of (1 << t*16)
    {
        const int t0 = tid & 3, t1 = (tid >> 2) & 3,
                  t2 = (tid >> 4) & 3, t3 = (tid >> 6) & 3;
        s_lut[tid] = (1ull << (t0 * 16)) + (1ull << (t1 * 16))
                   + (1ull << (t2 * 16)) + (1ull << (t3 * 16));
    }
    if (tid < CAP * NSUB) ((unsigned long long*)s_hist)[tid] = 0ull;
    __syncthreads();

    const int eA = s_eA, eB = s_eB;
    const int nown = eB - eA + 1;           // may be <=0: block writes nothing

    for (int cbase = 0; cbase < nown; cbase += CAP) {   // one pass normally
        const int fA = eA + cbase;
        const int fB = min(eB, fA + CAP - 1);
        const unsigned span = (unsigned)(fB - fA);

        // ---- deposit this thread's strip ----
        if (full) {
            if (sfirst == slast) {          // uniform strip (~94%)
                const int le = sfirst - fA;
                if ((unsigned)le <= span)
                    atomicAdd(&s_hist[le][lane & (NSUB - 1)],
                              s_lut[pk & 0xFF]         + s_lut[(pk >> 8) & 0xFF]
                            + s_lut[(pk >> 16) & 0xFF] + s_lut[(pk >> 24) & 0xFF]);
            } else {                        // boundary strip: walk runs
                const int4 sa = seg4[j],     sb = seg4[j + 1];   // L1 hits
                const int4 sc = seg4[j + 2], sd = seg4[j + 3];
                int cur = sa.x;
                unsigned long long run = 0ull;
#define DEP(C, R)                                                           \
                do {                                                        \
                    const int _le = (C) - fA;                               \
                    if ((R) && (unsigned)_le <= span)                       \
                        atomicAdd(&s_hist[_le][lane & (NSUB - 1)], (R));    \
                } while (0)
#define DOK(SK, K)                                                          \
                do {                                                        \
                    if ((SK) != cur) { DEP(cur, run); run = 0ull; cur = (SK); } \
                    run += 1ull << (((pk >> (2 * (K))) & 3) * 16);          \
                } while (0)
                DOK(sa.x, 0);  DOK(sa.y, 1);  DOK(sa.z, 2);  DOK(sa.w, 3);
                DOK(sb.x, 4);  DOK(sb.y, 5);  DOK(sb.z, 6);  DOK(sb.w, 7);
                DOK(sc.x, 8);  DOK(sc.y, 9);  DOK(sc.z, 10); DOK(sc.w, 11);
                DOK(sd.x, 12); DOK(sd.y, 13); DOK(sd.z, 14); DOK(sd.w, 15);
                DEP(cur, run);
#undef DOK
            }
        } else if (base < T) {              // ragged tail insurance
            for (int k = 0; k < 16 && base + k < T; k++) {
                const int s = __ldg(&segs[base + k]);
                const int le = s - fA;
                if ((unsigned)le <= span)
                    atomicAdd(&s_hist[le][lane & (NSUB - 1)],
                              1ull << ((__ldg(&tokens[base + k]) & 3) * 16));
            }
        }
        __syncthreads();

        // ---- epilogue ----
        const int d = lane * 4;
        const bool tailPass = (fB == eB);
        const int lastInt = tailPass ? fB - 1 : fB;   // warp 0 owns eB's row

        if (wid > 0 || !tailPass) {
            const int stride = tailPass ? 7 : 8;
            const int first  = tailPass ? fA + (wid - 1) : fA + wid;
            for (int e = first; e <= lastInt; e += stride) {
                const int le = e - fA;
                unsigned long long h = 0ull;
#pragma unroll
                for (int q = 0; q < NSUB; q++) h += s_hist[le][q];

                const float f0 = (float)((unsigned)(h      ) & 0xFFFFu);
                const float f1 = (float)((unsigned)(h >> 16) & 0xFFFFu);
                const float f2 = (float)((unsigned)(h >> 32) & 0xFFFFu);
                const float f3 = (float)((unsigned)(h >> 48) & 0xFFFFu);
                const float inv = 1.0f / fmaxf(f0 + f1 + f2 + f3, 1.0f);

                const float4 v0 = *(const float4*)(emb + 0 * OUT_CH + d);
                const float4 v1 = *(const float4*)(emb + 1 * OUT_CH + d);
                const float4 v2 = *(const float4*)(emb + 2 * OUT_CH + d);
                const float4 v3 = *(const float4*)(emb + 3 * OUT_CH + d);
                float4 r;
                r.x = (f0 * v0.x + f1 * v1.x + f2 * v2.x + f3 * v3.x) * inv;
                r.y = (f0 * v0.y + f1 * v1.y + f2 * v2.y + f3 * v3.y) * inv;
                r.z = (f0 * v0.z + f1 * v1.z + f2 * v2.z + f3 * v3.z) * inv;
                r.w = (f0 * v0.w + f1 * v1.w + f2 * v2.w + f3 * v3.w) * inv;
                *(float4*)(out + (long long)e * OUT_CH + d) = r;
            }
        }

        if (wid == 0 && tailPass) {
            // finish eB's spill into following windows, then write its row
            unsigned long long ext = 0ull;
            int pos = hi;
            while (pos < T) {
                const int idx = pos + lane * 4;
                int4 s4 = make_int4(-1, -1, -1, -1), t4;
                if (idx < T) {
                    const int jj = (pos >> 2) + lane;
                    s4 = seg4[jj]; t4 = tok4[jj];
                    if (s4.x == eB)                ext += 1ull << ((t4.x & 3) * 16);
                    if (idx + 1 < T && s4.y == eB) ext += 1ull << ((t4.y & 3) * 16);
                    if (idx + 2 < T && s4.z == eB) ext += 1ull << ((t4.z & 3) * 16);
                    if (idx + 3 < T && s4.w == eB) ext += 1ull << ((t4.w & 3) * 16);
                }
                const int lastIdx  = min(T, pos + 128) - 1;
                const int lastLane = (lastIdx - pos) >> 2;
                int sl = -1;
                if (lane == lastLane) {
                    const int rix = lastIdx - idx;
                    sl = (rix == 0) ? s4.x : (rix == 1) ? s4.y
                       : (rix == 2) ? s4.z : s4.w;
                }
                sl = __shfl_sync(0xFFFFFFFFu, sl, lastLane);
                pos += 128;
                if (sl != eB) break;
            }
            const unsigned xlo = __reduce_add_sync(0xFFFFFFFFu, (unsigned)ext);
            const unsigned xhi = __reduce_add_sync(0xFFFFFFFFu, (unsigned)(ext >> 32));

            unsigned long long h = 0ull;
#pragma unroll
            for (int q = 0; q < NSUB; q++) h += s_hist[eB - fA][q];

            const float f0 = (float)(((unsigned)(h      ) & 0xFFFFu) + (xlo & 0xFFFFu));
            const float f1 = (float)(((unsigned)(h >> 16) & 0xFFFFu) + (xlo >> 16));
            const float f2 = (float)(((unsigned)(h >> 32) & 0xFFFFu) + (xhi & 0xFFFFu));
            const float f3 = (float)(((unsigned)(h >> 48) & 0xFFFFu) + (xhi >> 16));
            const float inv = 1.0f / fmaxf(f0 + f1 + f2 + f3, 1.0f);

            const int d0 = lane * 4;
            const float4 v0 = *(const float4*)(emb + 0 * OUT_CH + d0);
            const float4 v1 = *(const float4*)(emb + 1 * OUT_CH + d0);
            const float4 v2 = *(const float4*)(emb + 2 * OUT_CH + d0);
            const float4 v3 = *(const float4*)(emb + 3 * OUT_CH + d0);
            float4 r;
            r.x = (f0 * v0.x + f1 * v1.x + f2 * v2.x + f3 * v3.x) * inv;
            r.y = (f0 * v0.y + f1 * v1.y + f2 * v2.y + f3 * v3.y) * inv;
            r.z = (f0 * v0.z + f1 * v1.z + f2 * v2.z + f3 * v3.z) * inv;
            r.w = (f0 * v0.w + f1 * v1.w + f2 * v2.w + f3 * v3.w) * inv;
            *(float4*)(out + (long long)eB * OUT_CH + d0) = r;
        }

        if (cbase + CAP < nown) {       // pathological multi-pass only
            __syncthreads();
            if (tid < CAP * NSUB) ((unsigned long long*)s_hist)[tid] = 0ull;
            __syncthreads();
        }
    }
}

extern "C" void kernel_launch(void* const* d_in, const int* in_sizes, int n_in,
                              void* d_out, int out_size) {
    // Inputs: 0 overlap_similarity f32[E], 1 overlap_length f32[E],
    //         2 tokens i32[T], 3 segment_ids i32[T], 4 embedding f32[4*128],
    //         5 n_edges
    const int*   tokens = (const int*)d_in[2];
    const int*   segs   = (const int*)d_in[3];
    const float* emb    = (const float*)d_in[4];
    float*       out    = (float*)d_out;

    const int T = in_sizes[2];
    const int E = out_size / OUT_CH;

    const int blocks = (T + TOKB - 1) / TOKB;   // 512
    fused_edge_mean<<<blocks, TPB>>>(tokens, segs, emb, out, T, E);
}